// round 8
// baseline (speedup 1.0000x reference)
#include <cuda_runtime.h>
#include <cuda_bf16.h>
#include <cstdint>

#define Bq   256
#define Tq   256
#define Cc   147
#define HDIM 64
#define NHH  4
#define HDd  16
#define BPMn 32

// ---------------- device scratch (allocation-free rule) ---------------------
__device__ __nv_bfloat16 g_qh[1024 * 256 * 16], g_ql[1024 * 256 * 16];
__device__ __nv_bfloat16 g_kh[1024 * 256 * 16], g_kl[1024 * 256 * 16];
__device__ __nv_bfloat16 g_vh[1024 * 256 * 16], g_vl[1024 * 256 * 16];
__device__ __nv_bfloat16 g_AoH[65536 * 64], g_AoL[65536 * 64];
__device__ uint2 g_fqH[24 * 10 * 32], g_fqL[24 * 10 * 32];
__device__ uint2 g_foH[20 * 4 * 32],  g_foL[20 * 4 * 32];
__device__ float g_bpmf[256 * 64];

// ---------------- helpers ---------------------------------------------------
__device__ __forceinline__ uint32_t smem_u32(const void* p) {
    uint32_t a;
    asm("{ .reg .u64 t; cvta.to.shared.u64 t, %1; cvt.u32.u64 %0, t; }" : "=r"(a) : "l"(p));
    return a;
}
__device__ __forceinline__ void mma_bf16(float* d, const uint32_t* a, const uint32_t* b) {
    asm volatile(
        "mma.sync.aligned.m16n8k16.row.col.f32.bf16.bf16.f32 "
        "{%0,%1,%2,%3}, {%4,%5,%6,%7}, {%8,%9}, {%0,%1,%2,%3};\n"
        : "+f"(d[0]), "+f"(d[1]), "+f"(d[2]), "+f"(d[3])
        : "r"(a[0]), "r"(a[1]), "r"(a[2]), "r"(a[3]), "r"(b[0]), "r"(b[1]));
}
__device__ __forceinline__ void ldsm4(uint32_t* r, uint32_t addr) {
    asm volatile("ldmatrix.sync.aligned.m8n8.x4.shared.b16 {%0,%1,%2,%3}, [%4];"
                 : "=r"(r[0]), "=r"(r[1]), "=r"(r[2]), "=r"(r[3]) : "r"(addr));
}
__device__ __forceinline__ void ldsm2(uint32_t* r, uint32_t addr) {
    asm volatile("ldmatrix.sync.aligned.m8n8.x2.shared.b16 {%0,%1}, [%2];"
                 : "=r"(r[0]), "=r"(r[1]) : "r"(addr));
}
__device__ __forceinline__ void ldsm2t(uint32_t* r, uint32_t addr) {
    asm volatile("ldmatrix.sync.aligned.m8n8.x2.trans.shared.b16 {%0,%1}, [%2];"
                 : "=r"(r[0]), "=r"(r[1]) : "r"(addr));
}
__device__ __forceinline__ void split_bf16(float f, __nv_bfloat16& hi, __nv_bfloat16& lo) {
    hi = __float2bfloat16(f);
    lo = __float2bfloat16(f - __bfloat162float(hi));
}
__device__ __forceinline__ void pack_hl(float e0, float e1, uint32_t& hi, uint32_t& lo) {
    __nv_bfloat16 h0, l0, h1, l1;
    split_bf16(e0, h0, l0);
    split_bf16(e1, h1, l1);
    __nv_bfloat162 H(h0, h1), L(l0, l1);
    hi = *(uint32_t*)&H;
    lo = *(uint32_t*)&L;
}
__device__ __forceinline__ uint32_t pack_h(float e0, float e1) {
    __nv_bfloat162 H(__float2bfloat16(e0), __float2bfloat16(e1));
    return *(uint32_t*)&H;
}

// ---------------------------------------------------------------------------
// Prep: weights in mma-B fragment order (hi/lo) + bpm features. (unchanged)
// ---------------------------------------------------------------------------
__global__ void prep_kernel(const float* __restrict__ Wq, const float* __restrict__ Wk,
                            const float* __restrict__ Wv, const float* __restrict__ Wo,
                            const float* __restrict__ Wb, const float* __restrict__ bb,
                            const float* __restrict__ bpm)
{
    int gid = blockIdx.x * 256 + threadIdx.x;
    if (gid < 7680) {
        int lane = gid & 31, t = gid >> 5;
        int ks = t % 10, NT = t / 10;
        int n = NT * 8 + (lane >> 2);
        int kb = ks * 16 + (lane & 3) * 2;
        const float* W = (n < 64) ? Wq : (n < 128) ? Wk : Wv;
        int nc = n & 63;
        float f[4];
        #pragma unroll
        for (int i = 0; i < 4; ++i) {
            int k = kb + (i >> 1) * 8 + (i & 1);
            f[i] = (k < 147) ? W[k * 64 + nc] : 0.f;
        }
        __nv_bfloat16 h[4], l[4];
        #pragma unroll
        for (int i = 0; i < 4; ++i) split_bf16(f[i], h[i], l[i]);
        __nv_bfloat162 H0(h[0], h[1]), H1(h[2], h[3]), L0(l[0], l[1]), L1(l[2], l[3]);
        g_fqH[gid] = make_uint2(*(uint32_t*)&H0, *(uint32_t*)&H1);
        g_fqL[gid] = make_uint2(*(uint32_t*)&L0, *(uint32_t*)&L1);
        return;
    }
    int j = gid - 7680;
    if (j < 2560) {
        int lane = j & 31, t = j >> 5;
        int ks = t & 3, NT = t >> 2;
        int n = NT * 8 + (lane >> 2);
        int kb = ks * 16 + (lane & 3) * 2;
        float f[4];
        #pragma unroll
        for (int i = 0; i < 4; ++i) {
            int k = kb + (i >> 1) * 8 + (i & 1);
            f[i] = (n < 147 && k < 64) ? Wo[k * 147 + n] : 0.f;
        }
        __nv_bfloat16 h[4], l[4];
        #pragma unroll
        for (int i = 0; i < 4; ++i) split_bf16(f[i], h[i], l[i]);
        __nv_bfloat162 H0(h[0], h[1]), H1(h[2], h[3]), L0(l[0], l[1]), L1(l[2], l[3]);
        g_foH[j] = make_uint2(*(uint32_t*)&H0, *(uint32_t*)&H1);
        g_foL[j] = make_uint2(*(uint32_t*)&L0, *(uint32_t*)&L1);
        return;
    }
    int i = j - 2560;
    if (i < 256 * 64) {
        int b = i >> 6, n = i & 63;
        float s = bb[n];
        #pragma unroll
        for (int q = 0; q < BPMn; ++q) s += bpm[b * BPMn + q] * Wb[q * 64 + n];
        g_bpmf[i] = s;
    }
}

// ---------------------------------------------------------------------------
// Kernel 1: fused QKV (unchanged from R7: grid=1024, 64 rows, 4m x 2n warps,
// one-kstep-ahead B prefetch).
// ---------------------------------------------------------------------------
#define SA1 168
#define Q_AH 0
#define Q_AL (Q_AH + 64 * SA1 * 2)     // 21504
#define SMEM1 (Q_AL + 64 * SA1 * 2)    // 43008

__global__ void __launch_bounds__(256) qkv_mma_kernel(
    const float* __restrict__ pose,
    const float* __restrict__ bq, const float* __restrict__ bk, const float* __restrict__ bv)
{
    extern __shared__ char sm[];
    __nv_bfloat16* Ah = (__nv_bfloat16*)(sm + Q_AH);
    __nv_bfloat16* Al = (__nv_bfloat16*)(sm + Q_AL);

    const int tid = threadIdx.x, wid = tid >> 5, lane = tid & 31;
    const int row0 = blockIdx.x * 64;
    const int b = row0 >> 8;
    const int tbase = row0 & 255;

    for (int idx = tid; idx < 64 * 13; idx += 256) {
        int r = idx / 13, c = 147 + idx % 13;
        Ah[r * SA1 + c] = __float2bfloat16(0.f);
        Al[r * SA1 + c] = __float2bfloat16(0.f);
    }
    for (int idx = tid; idx < 64 * 147; idx += 256) {
        int r = idx / 147, c = idx - r * 147;
        __nv_bfloat16 hi, lo; split_bf16(pose[(size_t)(row0 + r) * 147 + c], hi, lo);
        Ah[r * SA1 + c] = hi;
        Al[r * SA1 + c] = lo;
    }

    const uint32_t smb = smem_u32(sm);
    const int mw = wid & 3;
    const int nw = wid >> 2;
    const int ln = lane & 15;
    const uint32_t aAddrH = smb + Q_AH + (uint32_t)(((mw * 16 + ln) * SA1 + (lane >> 4) * 8) * 2);
    const uint32_t aAddrL = aAddrH + (Q_AL - Q_AH);
    __syncthreads();

    for (int c3 = 0; c3 < 3; ++c3) {
        const int NT0 = c3 * 8 + nw * 4;
        float d[4][4] = {};
        uint2 h2[4], l2[4], h2n[4], l2n[4];
        #pragma unroll
        for (int nt = 0; nt < 4; ++nt) {
            h2[nt] = g_fqH[((NT0 + nt) * 10) * 32 + lane];
            l2[nt] = g_fqL[((NT0 + nt) * 10) * 32 + lane];
        }
        #pragma unroll
        for (int ks = 0; ks < 10; ++ks) {
            uint32_t aH[4], aL[4];
            ldsm4(aH, aAddrH + ks * 32);
            ldsm4(aL, aAddrL + ks * 32);
            if (ks < 9) {
                #pragma unroll
                for (int nt = 0; nt < 4; ++nt) {
                    h2n[nt] = g_fqH[((NT0 + nt) * 10 + ks + 1) * 32 + lane];
                    l2n[nt] = g_fqL[((NT0 + nt) * 10 + ks + 1) * 32 + lane];
                }
            }
            #pragma unroll
            for (int nt = 0; nt < 4; ++nt) {
                uint32_t bH[2] = { h2[nt].x, h2[nt].y };
                uint32_t bL[2] = { l2[nt].x, l2[nt].y };
                mma_bf16(d[nt], aH, bH);
                mma_bf16(d[nt], aH, bL);
                mma_bf16(d[nt], aL, bH);
            }
            #pragma unroll
            for (int nt = 0; nt < 4; ++nt) { h2[nt] = h2n[nt]; l2[nt] = l2n[nt]; }
        }

        const float* bias = (c3 == 0) ? bq : (c3 == 1) ? bk : bv;
        __nv_bfloat16* dstH = (c3 == 0) ? g_qh : (c3 == 1) ? g_kh : g_vh;
        __nv_bfloat16* dstL = (c3 == 0) ? g_ql : (c3 == 1) ? g_kl : g_vl;
        uint32_t* dH = (uint32_t*)dstH;
        uint32_t* dL = (uint32_t*)dstL;
        const int r0 = mw * 16 + (lane >> 2);
        #pragma unroll
        for (int nt = 0; nt < 4; ++nt) {
            int lc = nw * 32 + nt * 8 + (lane & 3) * 2;
            int h = lc >> 4, dd = lc & 15;
            float b0 = __ldg(bias + lc), b1 = __ldg(bias + lc + 1);
            if (c3 == 1) { b0 += g_bpmf[b * 64 + lc]; b1 += g_bpmf[b * 64 + lc + 1]; }
            uint32_t base = (uint32_t)(((b * 4 + h) * 256) * 8 + dd / 2);
            uint32_t hi, lo;
            pack_hl(d[nt][0] + b0, d[nt][1] + b1, hi, lo);
            dH[base + (tbase + r0) * 8] = hi;
            dL[base + (tbase + r0) * 8] = lo;
            pack_hl(d[nt][2] + b0, d[nt][3] + b1, hi, lo);
            dH[base + (tbase + r0 + 8) * 8] = hi;
            dL[base + (tbase + r0 + 8) * 8] = lo;
        }
    }
}

// ---------------------------------------------------------------------------
// Kernel 2: tensor-core flash attention. grid=1024 (=bh), 256 thr.
// NEW: K and V both row-major in smem (stride 48B), staged with uint4 copies;
// V^T fragments come from ldmatrix.trans (no transpose pass, no 2B stores).
// Numerics identical to R7.
// ---------------------------------------------------------------------------
#define KVS 24     // row stride in bf16 (48B)

__global__ void __launch_bounds__(256) attn_mma_kernel()
{
    __shared__ __align__(16) __nv_bfloat16 khS[256 * KVS], klS[256 * KVS];
    __shared__ __align__(16) __nv_bfloat16 vhS[256 * KVS], vlS[256 * KVS];

    const int bh = blockIdx.x;
    const int tid = threadIdx.x, wid = tid >> 5, lane = tid & 31;

    // stage K/V hi/lo: 512 uint4 per array, 16B stores at stride-48B rows
    {
        const uint4* kh4 = (const uint4*)g_kh + (size_t)bh * 512;
        const uint4* kl4 = (const uint4*)g_kl + (size_t)bh * 512;
        const uint4* vh4 = (const uint4*)g_vh + (size_t)bh * 512;
        const uint4* vl4 = (const uint4*)g_vl + (size_t)bh * 512;
        #pragma unroll
        for (int i = tid; i < 512; i += 256) {
            int r = i >> 1, p = i & 1;
            uint32_t off = (uint32_t)(r * 48 + p * 16);
            *(uint4*)((char*)khS + off) = kh4[i];
            *(uint4*)((char*)klS + off) = kl4[i];
            *(uint4*)((char*)vhS + off) = vh4[i];
            *(uint4*)((char*)vlS + off) = vl4[i];
        }
    }

    // Q fragments direct from global (hi/lo, 2 m-tiles per warp)
    uint32_t qaH[2][4], qaL[2][4];
    {
        const uint32_t* qH = (const uint32_t*)g_qh + (size_t)bh * 2048;
        const uint32_t* qL = (const uint32_t*)g_ql + (size_t)bh * 2048;
        const int c = lane & 3;
        #pragma unroll
        for (int mt = 0; mt < 2; ++mt) {
            int r = wid * 32 + mt * 16 + (lane >> 2);
            qaH[mt][0] = qH[r * 8 + c];           qaL[mt][0] = qL[r * 8 + c];
            qaH[mt][1] = qH[(r + 8) * 8 + c];     qaL[mt][1] = qL[(r + 8) * 8 + c];
            qaH[mt][2] = qH[r * 8 + c + 4];       qaL[mt][2] = qL[r * 8 + c + 4];
            qaH[mt][3] = qH[(r + 8) * 8 + c + 4]; qaL[mt][3] = qL[(r + 8) * 8 + c + 4];
        }
    }
    __syncthreads();

    const uint32_t smbKh = smem_u32(khS);
    const uint32_t smbKl = smem_u32(klS);
    const uint32_t smbVh = smem_u32(vhS);
    const uint32_t smbVl = smem_u32(vlS);
    const int lr = lane & 7, lc = (lane >> 3) & 1;

    float cO[2][2][4] = {};
    float lacc[2][2] = {};

    for (int kc = 0; kc < 16; ++kc) {
        const int j0 = kc * 16;
        uint32_t bKh[2][2], bKl[2][2], bVh[2][2], bVl[2][2];
        #pragma unroll
        for (int nt = 0; nt < 2; ++nt) {
            // K (S-mma B): n-rows = key index, k-cols = head dim
            uint32_t ko = (uint32_t)(((j0 + nt * 8 + lr) * KVS + lc * 8) * 2);
            ldsm2(bKh[nt], smbKh + ko);
            ldsm2(bKl[nt], smbKl + ko);
            // V (O-mma B) via trans-ldsm on row-major V: rows = key index,
            // cols = head dim (n). lanes 0-7 -> k j0..j0+7 (b0), 8-15 -> +8 (b1).
            uint32_t vo = (uint32_t)(((j0 + lc * 8 + lr) * KVS + nt * 8) * 2);
            ldsm2t(bVh[nt], smbVh + vo);
            ldsm2t(bVl[nt], smbVl + vo);
        }
        #pragma unroll
        for (int mt = 0; mt < 2; ++mt) {
            float s[2][4] = {};
            #pragma unroll
            for (int nt = 0; nt < 2; ++nt) {
                mma_bf16(s[nt], qaH[mt], bKh[nt]);
                mma_bf16(s[nt], qaH[mt], bKl[nt]);
                mma_bf16(s[nt], qaL[mt], bKh[nt]);
            }
            float e[2][4];
            #pragma unroll
            for (int nt = 0; nt < 2; ++nt)
                #pragma unroll
                for (int i = 0; i < 4; ++i)
                    e[nt][i] = __expf(s[nt][i] * 0.25f);
            lacc[mt][0] += e[0][0] + e[0][1] + e[1][0] + e[1][1];
            lacc[mt][1] += e[0][2] + e[0][3] + e[1][2] + e[1][3];
            uint32_t pH[4];
            pH[0] = pack_h(e[0][0], e[0][1]);
            pH[1] = pack_h(e[0][2], e[0][3]);
            pH[2] = pack_h(e[1][0], e[1][1]);
            pH[3] = pack_h(e[1][2], e[1][3]);
            #pragma unroll
            for (int nt = 0; nt < 2; ++nt) {
                mma_bf16(cO[mt][nt], pH, bVh[nt]);
                mma_bf16(cO[mt][nt], pH, bVl[nt]);
            }
        }
    }

    const int b = bh >> 2, h = bh & 3;
    uint32_t* aoH = (uint32_t*)g_AoH;
    uint32_t* aoL = (uint32_t*)g_AoL;
    #pragma unroll
    for (int mt = 0; mt < 2; ++mt) {
        float l0 = lacc[mt][0], l1 = lacc[mt][1];
        l0 += __shfl_xor_sync(0xffffffffu, l0, 1);
        l0 += __shfl_xor_sync(0xffffffffu, l0, 2);
        l1 += __shfl_xor_sync(0xffffffffu, l1, 1);
        l1 += __shfl_xor_sync(0xffffffffu, l1, 2);
        float inv0 = 1.f / l0, inv1 = 1.f / l1;
        int r = wid * 32 + mt * 16 + (lane >> 2);
        #pragma unroll
        for (int nt = 0; nt < 2; ++nt) {
            int n0 = nt * 8 + (lane & 3) * 2;
            uint32_t i0 = (uint32_t)((b * 256 + r) * 32 + h * 8 + n0 / 2);
            uint32_t i1 = i0 + 8 * 32;
            uint32_t hi, lo;
            pack_hl(cO[mt][nt][0] * inv0, cO[mt][nt][1] * inv0, hi, lo);
            aoH[i0] = hi; aoL[i0] = lo;
            pack_hl(cO[mt][nt][2] * inv1, cO[mt][nt][3] * inv1, hi, lo);
            aoH[i1] = hi; aoL[i1] = lo;
        }
    }
}

// ---------------------------------------------------------------------------
// Kernel 3: output projection (unchanged from R7). grid=2048, 256 thr.
// ---------------------------------------------------------------------------
#define OS2 72           // smem A row stride in bf16 (144B)

__global__ void __launch_bounds__(256) outproj_mma_kernel(
    const float* __restrict__ bo, float* __restrict__ out)
{
    __shared__ __align__(16) __nv_bfloat16 AhS[32 * OS2], AlS[32 * OS2];

    const int tid = threadIdx.x, wid = tid >> 5, lane = tid & 31;
    const int mw = wid & 1;
    const int ng = wid >> 1;
    const int row0 = blockIdx.x * 32;

    {
        const uint4* srcH = (const uint4*)g_AoH + (size_t)row0 * 8;
        const uint4* srcL = (const uint4*)g_AoL + (size_t)row0 * 8;
        int r = tid >> 3, c16 = tid & 7;
        *(uint4*)((char*)AhS + r * (OS2 * 2) + c16 * 16) = srcH[r * 8 + c16];
        *(uint4*)((char*)AlS + r * (OS2 * 2) + c16 * 16) = srcL[r * 8 + c16];
    }
    __syncthreads();

    const uint32_t smbH = smem_u32(AhS);
    const uint32_t smbL = smem_u32(AlS);
    const int ln = lane & 15;
    const uint32_t aAddrH = smbH + (uint32_t)(((mw * 16 + ln) * OS2 + (lane >> 4) * 8) * 2);
    const uint32_t aAddrL = smbL + (uint32_t)(((mw * 16 + ln) * OS2 + (lane >> 4) * 8) * 2);

    float d[5][4] = {};
    uint2 h2[5], l2[5], h2n[5], l2n[5];
    #pragma unroll
    for (int nt = 0; nt < 5; ++nt) {
        int NT = ng * 5 + nt;
        h2[nt] = g_foH[(NT * 4) * 32 + lane];
        l2[nt] = g_foL[(NT * 4) * 32 + lane];
    }
    #pragma unroll
    for (int ks = 0; ks < 4; ++ks) {
        uint32_t aHf[4], aLf[4];
        ldsm4(aHf, aAddrH + ks * 32);
        ldsm4(aLf, aAddrL + ks * 32);
        if (ks < 3) {
            #pragma unroll
            for (int nt = 0; nt < 5; ++nt) {
                int NT = ng * 5 + nt;
                h2n[nt] = g_foH[(NT * 4 + ks + 1) * 32 + lane];
                l2n[nt] = g_foL[(NT * 4 + ks + 1) * 32 + lane];
            }
        }
        #pragma unroll
        for (int nt = 0; nt < 5; ++nt) {
            uint32_t bH[2] = { h2[nt].x, h2[nt].y };
            uint32_t bL[2] = { l2[nt].x, l2[nt].y };
            mma_bf16(d[nt], aHf, bH);
            mma_bf16(d[nt], aHf, bL);
            mma_bf16(d[nt], aLf, bH);
        }
        #pragma unroll
        for (int nt = 0; nt < 5; ++nt) { h2[nt] = h2n[nt]; l2[nt] = l2n[nt]; }
    }

    int r = row0 + mw * 16 + (lane >> 2);
    float* o0 = out + (size_t)r * 147;
    float* o1 = o0 + 8 * 147;
    #pragma unroll
    for (int nt = 0; nt < 5; ++nt) {
        int c = (ng * 5 + nt) * 8 + (lane & 3) * 2;
        if (c < 147) {
            float bb0 = __ldg(bo + c);
            o0[c] = d[nt][0] + bb0;
            o1[c] = d[nt][2] + bb0;
        }
        if (c + 1 < 147) {
            float bb1 = __ldg(bo + c + 1);
            o0[c + 1] = d[nt][1] + bb1;
            o1[c + 1] = d[nt][3] + bb1;
        }
    }
}

// ---------------------------------------------------------------------------
extern "C" void kernel_launch(void* const* d_in, const int* in_sizes, int n_in,
                              void* d_out, int out_size)
{
    const float* pose = (const float*)d_in[0];
    const float* bpm  = (const float*)d_in[1];
    const float* Wq   = (const float*)d_in[2];
    const float* bq   = (const float*)d_in[3];
    const float* Wk   = (const float*)d_in[4];
    const float* bk   = (const float*)d_in[5];
    const float* Wv   = (const float*)d_in[6];
    const float* bv   = (const float*)d_in[7];
    const float* Wb   = (const float*)d_in[8];
    const float* bb   = (const float*)d_in[9];
    const float* Wo   = (const float*)d_in[10];
    const float* bo   = (const float*)d_in[11];
    float* out = (float*)d_out;

    cudaFuncSetAttribute(qkv_mma_kernel, cudaFuncAttributeMaxDynamicSharedMemorySize, SMEM1);

    prep_kernel<<<104, 256>>>(Wq, Wk, Wv, Wo, Wb, bb, bpm);
    qkv_mma_kernel<<<1024, 256, SMEM1>>>(pose, bq, bk, bv);
    attn_mma_kernel<<<1024, 256>>>();
    outproj_mma_kernel<<<2048, 256>>>(bo, out);
}

// round 9
// speedup vs baseline: 1.0854x; 1.0854x over previous
#include <cuda_runtime.h>
#include <cuda_bf16.h>
#include <cstdint>

#define Bq   256
#define Tq   256
#define Cc   147
#define HDIM 64
#define NHH  4
#define HDd  16
#define BPMn 32

// ---------------- device scratch (allocation-free rule) ---------------------
__device__ __nv_bfloat16 g_qh[1024 * 256 * 16], g_ql[1024 * 256 * 16];
__device__ __nv_bfloat16 g_kh[1024 * 256 * 16], g_kl[1024 * 256 * 16];
__device__ __nv_bfloat16 g_vh[1024 * 256 * 16], g_vl[1024 * 256 * 16];
__device__ __nv_bfloat16 g_AoH[65536 * 64], g_AoL[65536 * 64];
__device__ uint2 g_fqH[24 * 10 * 32], g_fqL[24 * 10 * 32];
__device__ uint2 g_foH[20 * 4 * 32],  g_foL[20 * 4 * 32];
__device__ float g_bpmf[256 * 64];

// ---------------- helpers ---------------------------------------------------
__device__ __forceinline__ uint32_t smem_u32(const void* p) {
    uint32_t a;
    asm("{ .reg .u64 t; cvta.to.shared.u64 t, %1; cvt.u32.u64 %0, t; }" : "=r"(a) : "l"(p));
    return a;
}
__device__ __forceinline__ void mma_bf16(float* d, const uint32_t* a, const uint32_t* b) {
    asm volatile(
        "mma.sync.aligned.m16n8k16.row.col.f32.bf16.bf16.f32 "
        "{%0,%1,%2,%3}, {%4,%5,%6,%7}, {%8,%9}, {%0,%1,%2,%3};\n"
        : "+f"(d[0]), "+f"(d[1]), "+f"(d[2]), "+f"(d[3])
        : "r"(a[0]), "r"(a[1]), "r"(a[2]), "r"(a[3]), "r"(b[0]), "r"(b[1]));
}
__device__ __forceinline__ void ldsm4(uint32_t* r, uint32_t addr) {
    asm volatile("ldmatrix.sync.aligned.m8n8.x4.shared.b16 {%0,%1,%2,%3}, [%4];"
                 : "=r"(r[0]), "=r"(r[1]), "=r"(r[2]), "=r"(r[3]) : "r"(addr));
}
__device__ __forceinline__ void ldsm2(uint32_t* r, uint32_t addr) {
    asm volatile("ldmatrix.sync.aligned.m8n8.x2.shared.b16 {%0,%1}, [%2];"
                 : "=r"(r[0]), "=r"(r[1]) : "r"(addr));
}
__device__ __forceinline__ void split_bf16(float f, __nv_bfloat16& hi, __nv_bfloat16& lo) {
    hi = __float2bfloat16(f);
    lo = __float2bfloat16(f - __bfloat162float(hi));
}
__device__ __forceinline__ void pack_hl(float e0, float e1, uint32_t& hi, uint32_t& lo) {
    __nv_bfloat16 h0, l0, h1, l1;
    split_bf16(e0, h0, l0);
    split_bf16(e1, h1, l1);
    __nv_bfloat162 H(h0, h1), L(l0, l1);
    hi = *(uint32_t*)&H;
    lo = *(uint32_t*)&L;
}
__device__ __forceinline__ uint32_t pack_h(float e0, float e1) {
    __nv_bfloat162 H(__float2bfloat16(e0), __float2bfloat16(e1));
    return *(uint32_t*)&H;
}

// ---------------------------------------------------------------------------
// Prep: weights in mma-B fragment order (hi/lo) + bpm features. (unchanged)
// ---------------------------------------------------------------------------
__global__ void prep_kernel(const float* __restrict__ Wq, const float* __restrict__ Wk,
                            const float* __restrict__ Wv, const float* __restrict__ Wo,
                            const float* __restrict__ Wb, const float* __restrict__ bb,
                            const float* __restrict__ bpm)
{
    int gid = blockIdx.x * 256 + threadIdx.x;
    if (gid < 7680) {
        int lane = gid & 31, t = gid >> 5;
        int ks = t % 10, NT = t / 10;
        int n = NT * 8 + (lane >> 2);
        int kb = ks * 16 + (lane & 3) * 2;
        const float* W = (n < 64) ? Wq : (n < 128) ? Wk : Wv;
        int nc = n & 63;
        float f[4];
        #pragma unroll
        for (int i = 0; i < 4; ++i) {
            int k = kb + (i >> 1) * 8 + (i & 1);
            f[i] = (k < 147) ? W[k * 64 + nc] : 0.f;
        }
        __nv_bfloat16 h[4], l[4];
        #pragma unroll
        for (int i = 0; i < 4; ++i) split_bf16(f[i], h[i], l[i]);
        __nv_bfloat162 H0(h[0], h[1]), H1(h[2], h[3]), L0(l[0], l[1]), L1(l[2], l[3]);
        g_fqH[gid] = make_uint2(*(uint32_t*)&H0, *(uint32_t*)&H1);
        g_fqL[gid] = make_uint2(*(uint32_t*)&L0, *(uint32_t*)&L1);
        return;
    }
    int j = gid - 7680;
    if (j < 2560) {
        int lane = j & 31, t = j >> 5;
        int ks = t & 3, NT = t >> 2;
        int n = NT * 8 + (lane >> 2);
        int kb = ks * 16 + (lane & 3) * 2;
        float f[4];
        #pragma unroll
        for (int i = 0; i < 4; ++i) {
            int k = kb + (i >> 1) * 8 + (i & 1);
            f[i] = (n < 147 && k < 64) ? Wo[k * 147 + n] : 0.f;
        }
        __nv_bfloat16 h[4], l[4];
        #pragma unroll
        for (int i = 0; i < 4; ++i) split_bf16(f[i], h[i], l[i]);
        __nv_bfloat162 H0(h[0], h[1]), H1(h[2], h[3]), L0(l[0], l[1]), L1(l[2], l[3]);
        g_foH[j] = make_uint2(*(uint32_t*)&H0, *(uint32_t*)&H1);
        g_foL[j] = make_uint2(*(uint32_t*)&L0, *(uint32_t*)&L1);
        return;
    }
    int i = j - 2560;
    if (i < 256 * 64) {
        int b = i >> 6, n = i & 63;
        float s = bb[n];
        #pragma unroll
        for (int q = 0; q < BPMn; ++q) s += bpm[b * BPMn + q] * Wb[q * 64 + n];
        g_bpmf[i] = s;
    }
}

// ---------------------------------------------------------------------------
// Kernel 1: fused QKV (R7 structure; NEW: float4 bulk A-loads).
// grid=1024 (64 rows), 256 thr (4m x 2n warps), one-kstep-ahead B prefetch.
// ---------------------------------------------------------------------------
#define SA1 168
#define Q_AH 0
#define Q_AL (Q_AH + 64 * SA1 * 2)     // 21504
#define SMEM1 (Q_AL + 64 * SA1 * 2)    // 43008

__global__ void __launch_bounds__(256) qkv_mma_kernel(
    const float* __restrict__ pose,
    const float* __restrict__ bq, const float* __restrict__ bk, const float* __restrict__ bv)
{
    extern __shared__ char sm[];
    __nv_bfloat16* Ah = (__nv_bfloat16*)(sm + Q_AH);
    __nv_bfloat16* Al = (__nv_bfloat16*)(sm + Q_AL);

    const int tid = threadIdx.x, wid = tid >> 5, lane = tid & 31;
    const int row0 = blockIdx.x * 64;
    const int b = row0 >> 8;
    const int tbase = row0 & 255;

    for (int idx = tid; idx < 64 * 13; idx += 256) {
        int r = idx / 13, c = 147 + idx % 13;
        Ah[r * SA1 + c] = __float2bfloat16(0.f);
        Al[r * SA1 + c] = __float2bfloat16(0.f);
    }
    // A tile via float4 bulk loads: 64*147 = 9408 floats = 2352 float4
    {
        const float4* pp4 = (const float4*)(pose + (size_t)row0 * 147);
        for (int i4 = tid; i4 < 2352; i4 += 256) {
            float4 v = pp4[i4];
            int e = i4 * 4;
            int r = e / 147, c = e - r * 147;
            float vv[4] = { v.x, v.y, v.z, v.w };
            #pragma unroll
            for (int j = 0; j < 4; ++j) {
                __nv_bfloat16 hi, lo; split_bf16(vv[j], hi, lo);
                Ah[r * SA1 + c] = hi;
                Al[r * SA1 + c] = lo;
                if (++c == 147) { c = 0; ++r; }
            }
        }
    }

    const uint32_t smb = smem_u32(sm);
    const int mw = wid & 3;
    const int nw = wid >> 2;
    const int ln = lane & 15;
    const uint32_t aAddrH = smb + Q_AH + (uint32_t)(((mw * 16 + ln) * SA1 + (lane >> 4) * 8) * 2);
    const uint32_t aAddrL = aAddrH + (Q_AL - Q_AH);
    __syncthreads();

    for (int c3 = 0; c3 < 3; ++c3) {
        const int NT0 = c3 * 8 + nw * 4;
        float d[4][4] = {};
        uint2 h2[4], l2[4], h2n[4], l2n[4];
        #pragma unroll
        for (int nt = 0; nt < 4; ++nt) {
            h2[nt] = g_fqH[((NT0 + nt) * 10) * 32 + lane];
            l2[nt] = g_fqL[((NT0 + nt) * 10) * 32 + lane];
        }
        #pragma unroll
        for (int ks = 0; ks < 10; ++ks) {
            uint32_t aH[4], aL[4];
            ldsm4(aH, aAddrH + ks * 32);
            ldsm4(aL, aAddrL + ks * 32);
            if (ks < 9) {
                #pragma unroll
                for (int nt = 0; nt < 4; ++nt) {
                    h2n[nt] = g_fqH[((NT0 + nt) * 10 + ks + 1) * 32 + lane];
                    l2n[nt] = g_fqL[((NT0 + nt) * 10 + ks + 1) * 32 + lane];
                }
            }
            #pragma unroll
            for (int nt = 0; nt < 4; ++nt) {
                uint32_t bH[2] = { h2[nt].x, h2[nt].y };
                uint32_t bL[2] = { l2[nt].x, l2[nt].y };
                mma_bf16(d[nt], aH, bH);
                mma_bf16(d[nt], aH, bL);
                mma_bf16(d[nt], aL, bH);
            }
            #pragma unroll
            for (int nt = 0; nt < 4; ++nt) { h2[nt] = h2n[nt]; l2[nt] = l2n[nt]; }
        }

        const float* bias = (c3 == 0) ? bq : (c3 == 1) ? bk : bv;
        __nv_bfloat16* dstH = (c3 == 0) ? g_qh : (c3 == 1) ? g_kh : g_vh;
        __nv_bfloat16* dstL = (c3 == 0) ? g_ql : (c3 == 1) ? g_kl : g_vl;
        uint32_t* dH = (uint32_t*)dstH;
        uint32_t* dL = (uint32_t*)dstL;
        const int r0 = mw * 16 + (lane >> 2);
        #pragma unroll
        for (int nt = 0; nt < 4; ++nt) {
            int lc = nw * 32 + nt * 8 + (lane & 3) * 2;
            int h = lc >> 4, dd = lc & 15;
            float b0 = __ldg(bias + lc), b1 = __ldg(bias + lc + 1);
            if (c3 == 1) { b0 += g_bpmf[b * 64 + lc]; b1 += g_bpmf[b * 64 + lc + 1]; }
            uint32_t base = (uint32_t)(((b * 4 + h) * 256) * 8 + dd / 2);
            uint32_t hi, lo;
            pack_hl(d[nt][0] + b0, d[nt][1] + b1, hi, lo);
            dH[base + (tbase + r0) * 8] = hi;
            dL[base + (tbase + r0) * 8] = lo;
            pack_hl(d[nt][2] + b0, d[nt][3] + b1, hi, lo);
            dH[base + (tbase + r0 + 8) * 8] = hi;
            dL[base + (tbase + r0 + 8) * 8] = lo;
        }
    }
}

// ---------------------------------------------------------------------------
// Kernel 2: tensor-core flash attention — exact R7 version (proven fastest).
// ---------------------------------------------------------------------------
#define KS  24
#define VTS 264

__global__ void __launch_bounds__(256) attn_mma_kernel()
{
    __shared__ __nv_bfloat16 khS[256 * KS], klS[256 * KS];
    __shared__ __nv_bfloat16 vtH[16 * VTS], vtL[16 * VTS];

    const int bh = blockIdx.x;
    const int tid = threadIdx.x, wid = tid >> 5, lane = tid & 31;

    {
        const uint32_t* kp = (const uint32_t*)g_kh + (size_t)bh * 2048;
        const uint32_t* lp = (const uint32_t*)g_kl + (size_t)bh * 2048;
        uint32_t* kd = (uint32_t*)khS;
        uint32_t* ld = (uint32_t*)klS;
        for (int idx = tid; idx < 2048; idx += 256) {
            int t = idx >> 3, dp = idx & 7;
            kd[t * (KS / 2) + dp] = kp[idx];
            ld[t * (KS / 2) + dp] = lp[idx];
        }
        const uint32_t* vp = (const uint32_t*)g_vh + (size_t)bh * 2048;
        const uint32_t* wp = (const uint32_t*)g_vl + (size_t)bh * 2048;
        for (int idx = tid; idx < 2048; idx += 256) {
            int t = idx >> 3, d0 = (idx & 7) * 2;
            __nv_bfloat162 v = *(const __nv_bfloat162*)&vp[idx];
            vtH[d0 * VTS + t] = v.x;
            vtH[(d0 + 1) * VTS + t] = v.y;
            __nv_bfloat162 w = *(const __nv_bfloat162*)&wp[idx];
            vtL[d0 * VTS + t] = w.x;
            vtL[(d0 + 1) * VTS + t] = w.y;
        }
    }

    uint32_t qaH[2][4], qaL[2][4];
    {
        const uint32_t* qH = (const uint32_t*)g_qh + (size_t)bh * 2048;
        const uint32_t* qL = (const uint32_t*)g_ql + (size_t)bh * 2048;
        const int c = lane & 3;
        #pragma unroll
        for (int mt = 0; mt < 2; ++mt) {
            int r = wid * 32 + mt * 16 + (lane >> 2);
            qaH[mt][0] = qH[r * 8 + c];           qaL[mt][0] = qL[r * 8 + c];
            qaH[mt][1] = qH[(r + 8) * 8 + c];     qaL[mt][1] = qL[(r + 8) * 8 + c];
            qaH[mt][2] = qH[r * 8 + c + 4];       qaL[mt][2] = qL[r * 8 + c + 4];
            qaH[mt][3] = qH[(r + 8) * 8 + c + 4]; qaL[mt][3] = qL[(r + 8) * 8 + c + 4];
        }
    }
    __syncthreads();

    const uint32_t smbK  = smem_u32(khS);
    const uint32_t smbKl = smem_u32(klS);
    const uint32_t smbVh = smem_u32(vtH);
    const uint32_t smbVl = smem_u32(vtL);
    const int lr = lane & 7, lc = (lane >> 3) & 1;

    float cO[2][2][4] = {};
    float lacc[2][2] = {};

    for (int kc = 0; kc < 16; ++kc) {
        const int j0 = kc * 16;
        uint32_t bKh[2][2], bKl[2][2], bVh[2][2], bVl[2][2];
        #pragma unroll
        for (int nt = 0; nt < 2; ++nt) {
            uint32_t ko = (uint32_t)(((j0 + nt * 8 + lr) * KS + lc * 8) * 2);
            ldsm2(bKh[nt], smbK + ko);
            ldsm2(bKl[nt], smbKl + ko);
            uint32_t vo = (uint32_t)(((nt * 8 + lr) * VTS + j0 + lc * 8) * 2);
            ldsm2(bVh[nt], smbVh + vo);
            ldsm2(bVl[nt], smbVl + vo);
        }
        #pragma unroll
        for (int mt = 0; mt < 2; ++mt) {
            float s[2][4] = {};
            #pragma unroll
            for (int nt = 0; nt < 2; ++nt) {
                mma_bf16(s[nt], qaH[mt], bKh[nt]);
                mma_bf16(s[nt], qaH[mt], bKl[nt]);
                mma_bf16(s[nt], qaL[mt], bKh[nt]);
            }
            float e[2][4];
            #pragma unroll
            for (int nt = 0; nt < 2; ++nt)
                #pragma unroll
                for (int i = 0; i < 4; ++i)
                    e[nt][i] = __expf(s[nt][i] * 0.25f);
            lacc[mt][0] += e[0][0] + e[0][1] + e[1][0] + e[1][1];
            lacc[mt][1] += e[0][2] + e[0][3] + e[1][2] + e[1][3];
            uint32_t pH[4];
            pH[0] = pack_h(e[0][0], e[0][1]);
            pH[1] = pack_h(e[0][2], e[0][3]);
            pH[2] = pack_h(e[1][0], e[1][1]);
            pH[3] = pack_h(e[1][2], e[1][3]);
            #pragma unroll
            for (int nt = 0; nt < 2; ++nt) {
                mma_bf16(cO[mt][nt], pH, bVh[nt]);
                mma_bf16(cO[mt][nt], pH, bVl[nt]);
            }
        }
    }

    const int b = bh >> 2, h = bh & 3;
    uint32_t* aoH = (uint32_t*)g_AoH;
    uint32_t* aoL = (uint32_t*)g_AoL;
    #pragma unroll
    for (int mt = 0; mt < 2; ++mt) {
        float l0 = lacc[mt][0], l1 = lacc[mt][1];
        l0 += __shfl_xor_sync(0xffffffffu, l0, 1);
        l0 += __shfl_xor_sync(0xffffffffu, l0, 2);
        l1 += __shfl_xor_sync(0xffffffffu, l1, 1);
        l1 += __shfl_xor_sync(0xffffffffu, l1, 2);
        float inv0 = 1.f / l0, inv1 = 1.f / l1;
        int r = wid * 32 + mt * 16 + (lane >> 2);
        #pragma unroll
        for (int nt = 0; nt < 2; ++nt) {
            int n0 = nt * 8 + (lane & 3) * 2;
            uint32_t i0 = (uint32_t)((b * 256 + r) * 32 + h * 8 + n0 / 2);
            uint32_t i1 = i0 + 8 * 32;
            uint32_t hi, lo;
            pack_hl(cO[mt][nt][0] * inv0, cO[mt][nt][1] * inv0, hi, lo);
            aoH[i0] = hi; aoL[i0] = lo;
            pack_hl(cO[mt][nt][2] * inv1, cO[mt][nt][3] * inv1, hi, lo);
            aoH[i1] = hi; aoL[i1] = lo;
        }
    }
}

// ---------------------------------------------------------------------------
// Kernel 3: output projection. grid=1024 (64 rows), 256 thr (2m x 4n warps).
// NEW: B fragments staged once per block into smem (read via LDS.64),
// 64-row M-tile halves per-block weight L2 traffic. Dynamic smem 59392B.
// ---------------------------------------------------------------------------
#define OS2 72
#define P3_AH 0
#define P3_AL (P3_AH + 64 * OS2 * 2)       // 9216
#define P3_BH (P3_AL + 64 * OS2 * 2)       // 18432
#define P3_BL (P3_BH + 2560 * 8)           // 38912
#define SMEM3 (P3_BL + 2560 * 8)           // 59392

__global__ void __launch_bounds__(256) outproj_mma_kernel(
    const float* __restrict__ bo, float* __restrict__ out)
{
    extern __shared__ char sm3[];
    uint2* BfH = (uint2*)(sm3 + P3_BH);
    uint2* BfL = (uint2*)(sm3 + P3_BL);

    const int tid = threadIdx.x, wid = tid >> 5, lane = tid & 31;
    const int mw = wid & 1;      // 2 m-warps x 32 rows (2 m-tiles each)
    const int ng = wid >> 1;     // 4 n-groups x 5 tiles
    const int row0 = blockIdx.x * 64;

    // stage A (64 rows x 128B, hi/lo) with uint4 coalesced copies
    {
        const uint4* srcH = (const uint4*)g_AoH + (size_t)row0 * 8;
        const uint4* srcL = (const uint4*)g_AoL + (size_t)row0 * 8;
        #pragma unroll
        for (int i = tid; i < 512; i += 256) {
            int r = i >> 3, c16 = i & 7;
            *(uint4*)(sm3 + P3_AH + r * (OS2 * 2) + c16 * 16) = srcH[i];
            *(uint4*)(sm3 + P3_AL + r * (OS2 * 2) + c16 * 16) = srcL[i];
        }
    }
    // stage B fragments (20KB hi + 20KB lo) with uint4 copies
    {
        const uint4* wH4 = (const uint4*)g_foH;
        const uint4* wL4 = (const uint4*)g_foL;
        #pragma unroll
        for (int i = tid; i < 1280; i += 256) {
            ((uint4*)BfH)[i] = wH4[i];
            ((uint4*)BfL)[i] = wL4[i];
        }
    }
    __syncthreads();

    const uint32_t smb = smem_u32(sm3);
    const int ln = lane & 15;

    float d[2][5][4] = {};
    #pragma unroll
    for (int ks = 0; ks < 4; ++ks) {
        uint32_t aHf[2][4], aLf[2][4];
        #pragma unroll
        for (int mt = 0; mt < 2; ++mt) {
            uint32_t ao = (uint32_t)(((mw * 32 + mt * 16 + ln) * OS2 + (lane >> 4) * 8) * 2) + ks * 32;
            ldsm4(aHf[mt], smb + P3_AH + ao);
            ldsm4(aLf[mt], smb + P3_AL + ao);
        }
        #pragma unroll
        for (int nt = 0; nt < 5; ++nt) {
            int fi = ((ng * 5 + nt) * 4 + ks) * 32 + lane;
            uint2 h2 = BfH[fi];
            uint2 l2 = BfL[fi];
            uint32_t bH[2] = { h2.x, h2.y };
            uint32_t bL[2] = { l2.x, l2.y };
            #pragma unroll
            for (int mt = 0; mt < 2; ++mt) {
                mma_bf16(d[mt][nt], aHf[mt], bH);
                mma_bf16(d[mt][nt], aHf[mt], bL);
                mma_bf16(d[mt][nt], aLf[mt], bH);
            }
        }
    }

    #pragma unroll
    for (int mt = 0; mt < 2; ++mt) {
        int r = row0 + mw * 32 + mt * 16 + (lane >> 2);
        float* o0 = out + (size_t)r * 147;
        float* o1 = o0 + 8 * 147;
        #pragma unroll
        for (int nt = 0; nt < 5; ++nt) {
            int c = (ng * 5 + nt) * 8 + (lane & 3) * 2;
            if (c < 147) {
                float bb0 = __ldg(bo + c);
                o0[c] = d[mt][nt][0] + bb0;
                o1[c] = d[mt][nt][2] + bb0;
            }
            if (c + 1 < 147) {
                float bb1 = __ldg(bo + c + 1);
                o0[c + 1] = d[mt][nt][1] + bb1;
                o1[c + 1] = d[mt][nt][3] + bb1;
            }
        }
    }
}

// ---------------------------------------------------------------------------
extern "C" void kernel_launch(void* const* d_in, const int* in_sizes, int n_in,
                              void* d_out, int out_size)
{
    const float* pose = (const float*)d_in[0];
    const float* bpm  = (const float*)d_in[1];
    const float* Wq   = (const float*)d_in[2];
    const float* bq   = (const float*)d_in[3];
    const float* Wk   = (const float*)d_in[4];
    const float* bk   = (const float*)d_in[5];
    const float* Wv   = (const float*)d_in[6];
    const float* bv   = (const float*)d_in[7];
    const float* Wb   = (const float*)d_in[8];
    const float* bb   = (const float*)d_in[9];
    const float* Wo   = (const float*)d_in[10];
    const float* bo   = (const float*)d_in[11];
    float* out = (float*)d_out;

    cudaFuncSetAttribute(qkv_mma_kernel,     cudaFuncAttributeMaxDynamicSharedMemorySize, SMEM1);
    cudaFuncSetAttribute(outproj_mma_kernel, cudaFuncAttributeMaxDynamicSharedMemorySize, SMEM3);

    prep_kernel<<<104, 256>>>(Wq, Wk, Wv, Wo, Wb, bb, bpm);
    qkv_mma_kernel<<<1024, 256, SMEM1>>>(pose, bq, bk, bv);
    attn_mma_kernel<<<1024, 256>>>();
    outproj_mma_kernel<<<1024, 256, SMEM3>>>(bo, out);
}